// round 14
// baseline (speedup 1.0000x reference)
#include <cuda_runtime.h>

// Clifford geometric product in Cl(3,0,0), blade order (grade-lex):
//   0:1, 1:e1, 2:e2, 3:e3, 4:e12, 5:e13, 6:e23, 7:e123
// out = a * b with hardcoded Cayley signs (metric = +1,+1,+1).
// Streaming kernel: 2 multivectors per thread, float4 I/O, 8 front-batched
// LDG.128 per thread (MLP_p1=8), streaming cache hints (__ldcs/__stcs)
// since every byte is touched exactly once.

__device__ __forceinline__ void gp8(
    const float4 al, const float4 ah,
    const float4 bl, const float4 bh,
    float4& ol, float4& oh)
{
    const float a0 = al.x, a1 = al.y, a2 = al.z, a3 = al.w;
    const float a4_ = ah.x, a5 = ah.y, a6 = ah.z, a7 = ah.w;
    const float b0 = bl.x, b1 = bl.y, b2 = bl.z, b3 = bl.w;
    const float b4_ = bh.x, b5 = bh.y, b6 = bh.z, b7 = bh.w;

    ol.x = a0*b0 + a1*b1 + a2*b2 + a3*b3 - a4_*b4_ - a5*b5 - a6*b6 - a7*b7;
    ol.y = a0*b1 + a1*b0 - a2*b4_ - a3*b5 + a4_*b2 + a5*b3 - a6*b7 - a7*b6;
    ol.z = a0*b2 + a1*b4_ + a2*b0 - a3*b6 - a4_*b1 + a5*b7 + a6*b3 + a7*b5;
    ol.w = a0*b3 + a1*b5 + a2*b6 + a3*b0 - a4_*b7 - a5*b1 - a6*b2 - a7*b4_;
    oh.x = a0*b4_ + a1*b2 - a2*b1 + a3*b7 + a4_*b0 - a5*b6 + a6*b5 + a7*b3;
    oh.y = a0*b5 + a1*b3 - a2*b7 - a3*b1 + a4_*b6 + a5*b0 - a6*b4_ - a7*b2;
    oh.z = a0*b6 + a1*b7 + a2*b3 - a3*b2 - a4_*b5 + a5*b4_ + a6*b0 + a7*b1;
    oh.w = a0*b7 + a1*b6 - a2*b5 + a3*b4_ + a4_*b3 - a5*b2 + a6*b1 + a7*b0;
}

__global__ void __launch_bounds__(256) clifford_gp_kernel2(
    const float4* __restrict__ a4,
    const float4* __restrict__ b4,
    float4* __restrict__ o4,
    int n_mv)  // n_mv is even (65536*64)
{
    int t = blockIdx.x * blockDim.x + threadIdx.x;  // one thread = 2 multivectors
    long long base = (long long)t * 4;              // float4 index of first of 4 float4s
    if (2 * t >= n_mv) return;

    // Front-batch all 8 input loads (streaming: data is single-use).
    const float4 a0l = __ldcs(&a4[base + 0]);
    const float4 a0h = __ldcs(&a4[base + 1]);
    const float4 a1l = __ldcs(&a4[base + 2]);
    const float4 a1h = __ldcs(&a4[base + 3]);
    const float4 b0l = __ldcs(&b4[base + 0]);
    const float4 b0h = __ldcs(&b4[base + 1]);
    const float4 b1l = __ldcs(&b4[base + 2]);
    const float4 b1h = __ldcs(&b4[base + 3]);

    float4 o0l, o0h, o1l, o1h;
    gp8(a0l, a0h, b0l, b0h, o0l, o0h);
    gp8(a1l, a1h, b1l, b1h, o1l, o1h);

    __stcs(&o4[base + 0], o0l);
    __stcs(&o4[base + 1], o0h);
    __stcs(&o4[base + 2], o1l);
    __stcs(&o4[base + 3], o1h);
}

extern "C" void kernel_launch(void* const* d_in, const int* in_sizes, int n_in,
                              void* d_out, int out_size)
{
    const float4* a4 = (const float4*)d_in[0];
    const float4* b4 = (const float4*)d_in[1];
    // d_in[2] = cayley[8,8,8] — deterministic for METRIC=(1,1,1); signs are baked in.
    float4* o4 = (float4*)d_out;

    int n_mv = in_sizes[0] / 8;              // number of multivectors
    int n_threads = (n_mv + 1) / 2;          // 2 multivectors per thread
    int threads = 256;
    int blocks = (n_threads + threads - 1) / threads;
    clifford_gp_kernel2<<<blocks, threads>>>(a4, b4, o4, n_mv);
}